// round 3
// baseline (speedup 1.0000x reference)
#include <cuda_runtime.h>
#include <math.h>

#define BATCH 8
#define HW    262144   // 512*512, = 1<<18
#define SPIX  256
#define FEAT  64
#define RREP  8        // replication factor for moment table (atomic dilution)

// Scratch (allocation-free): replicated moment table + normalized reduced feats.
// Moment layout per (rep,b,s): 12 floats {n, sx0, sx1, sx2, s00, s01, s02, s11, s12, s22, pad, pad}
__device__ float g_mom[RREP * BATCH * SPIX * 12];
__device__ float g_rn[BATCH * SPIX * FEAT];

// ---------------------------------------------------------------------------
// Kernel 0: zero the moment table (graph replays must be deterministic)
// ---------------------------------------------------------------------------
__global__ void zero_kernel() {
    int n = RREP * BATCH * SPIX * 12;
    for (int i = blockIdx.x * blockDim.x + threadIdx.x; i < n;
         i += gridDim.x * blockDim.x)
        g_mom[i] = 0.0f;
}

// ---------------------------------------------------------------------------
// Kernel 1: per-pixel scatter of x-moments via vector global reductions
// ---------------------------------------------------------------------------
__device__ __forceinline__ void red4(float* p, float a, float b, float c, float d) {
    unsigned long long g;
    asm volatile("cvta.to.global.u64 %0, %1;" : "=l"(g) : "l"(p));
    asm volatile("red.global.add.v4.f32 [%0], {%1,%2,%3,%4};"
                 :: "l"(g), "f"(a), "f"(b), "f"(c), "f"(d) : "memory");
}

__global__ void moments_kernel(const float* __restrict__ x,
                               const int* __restrict__ lab) {
    const int rep = blockIdx.x & (RREP - 1);
    const int stride = gridDim.x * blockDim.x;
    for (int p = blockIdx.x * blockDim.x + threadIdx.x; p < BATCH * HW; p += stride) {
        int b  = p >> 18;          // HW = 2^18
        int hw = p & (HW - 1);
        const float* xb = x + (size_t)b * 3 * HW + hw;
        float x0 = xb[0];
        float x1 = xb[HW];
        float x2 = xb[2 * HW];
        int s = lab[p] & (SPIX - 1);
        float* dst = g_mom + ((size_t)((rep * BATCH + b) * SPIX + s)) * 12;
        red4(dst,     1.0f,    x0,      x1,      x2);
        red4(dst + 4, x0 * x0, x0 * x1, x0 * x2, x1 * x1);
        red4(dst + 8, x1 * x2, x2 * x2, 0.0f,    0.0f);
    }
}

// ---------------------------------------------------------------------------
// Kernel 2: moments -> mean/std -> W_red matvec -> L2 normalize  (fused)
// 256 blocks x 256 threads; warp w handles segment s = (blk&31)*8 + w.
// Lane handles channels {lane, lane+32}.
// ---------------------------------------------------------------------------
__global__ void stats_kernel(const float* __restrict__ W_pix,
                             const float* __restrict__ b_pix,
                             const float* __restrict__ W_red,
                             const float* __restrict__ b_red) {
    __shared__ float s_wt[128 * 64];    // W_red transposed: [g][f]
    __shared__ float s_comb[8][128];    // per-warp combined [mean;std]

    int tid = threadIdx.x;
    for (int idx = tid; idx < 8192; idx += 256) {
        int f = idx >> 7, g = idx & 127;
        s_wt[g * 64 + f] = W_red[idx];  // coalesced read, transposed store
    }
    __syncthreads();

    int w = tid >> 5, lane = tid & 31;
    int b = blockIdx.x >> 5;
    int s = (blockIdx.x & 31) * 8 + w;

    // Reduce replicas (warp-uniform addresses -> broadcast loads)
    float mom[10];
#pragma unroll
    for (int j = 0; j < 10; j++) mom[j] = 0.0f;
    const float* mp = g_mom + ((size_t)(b * SPIX + s)) * 12;
#pragma unroll
    for (int r = 0; r < RREP; r++) {
        const float* m = mp + (size_t)r * BATCH * SPIX * 12;
#pragma unroll
        for (int j = 0; j < 10; j++) mom[j] += m[j];
    }

    float cnt = mom[0];
    float inv = 1.0f / fmaxf(cnt, 1.0f);
    float cn  = cnt * inv;  // 1 if nonempty, 0 if empty (matches ref clamp)
    float mx0 = mom[1] * inv, mx1 = mom[2] * inv, mx2 = mom[3] * inv;
    float M00 = mom[4] * inv, M01 = mom[5] * inv, M02 = mom[6] * inv;
    float M11 = mom[7] * inv, M12 = mom[8] * inv, M22 = mom[9] * inv;

#pragma unroll
    for (int c = 0; c < 2; c++) {
        int f = lane + c * 32;
        float w0 = W_pix[3 * f], w1 = W_pix[3 * f + 1], w2 = W_pix[3 * f + 2];
        float bp = b_pix[f];
        float d = w0 * mx0 + w1 * mx1 + w2 * mx2;
        float q = w0 * w0 * M00 + w1 * w1 * M11 + w2 * w2 * M22
                + 2.0f * (w0 * w1 * M01 + w0 * w2 * M02 + w1 * w2 * M12);
        float mean = d + bp * cn;
        float e2   = q + 2.0f * bp * d + bp * bp * cn;
        float var  = e2 - mean * mean;
        float sd   = sqrtf(fmaxf(var, 1e-6f));
        s_comb[w][f]      = mean;
        s_comb[w][64 + f] = sd;
    }
    __syncwarp();

    // reduced = W_red @ combined + b_red ; lane owns outputs {lane, lane+32}
    float r0 = b_red[lane], r1 = b_red[lane + 32];
#pragma unroll 8
    for (int g = 0; g < 128; g++) {
        float cg = s_comb[w][g];              // broadcast
        r0 += s_wt[g * 64 + lane]      * cg;  // conflict-free (stride 1)
        r1 += s_wt[g * 64 + lane + 32] * cg;
    }

    // L2 normalize across 64 channels (warp allreduce)
    float ss = r0 * r0 + r1 * r1;
#pragma unroll
    for (int o = 16; o > 0; o >>= 1) ss += __shfl_xor_sync(0xffffffffu, ss, o);
    float invn = 1.0f / fmaxf(sqrtf(ss), 1e-12f);

    float* out = g_rn + ((size_t)(b * SPIX + s)) * FEAT;
    out[lane]      = r0 * invn;
    out[lane + 32] = r1 * invn;
}

// ---------------------------------------------------------------------------
// Kernel 3: sim = rn @ rn^T, then fused affine(conv1x1 + BN) + ReLU
// grid (8,8,8) = (j-tile, i-tile, batch); block (32,32)
// ---------------------------------------------------------------------------
__global__ void sim_kernel(const float* __restrict__ w_sim,
                           const float* __restrict__ b_sim,
                           const float* __restrict__ gma,
                           const float* __restrict__ bta,
                           const float* __restrict__ mu,
                           const float* __restrict__ vr,
                           float* __restrict__ out) {
    __shared__ float ti[32][65];
    __shared__ float tj[32][65];
    int b = blockIdx.z, i0 = blockIdx.y * 32, j0 = blockIdx.x * 32;
    int tx = threadIdx.x, ty = threadIdx.y;
    int tid = ty * 32 + tx;

    for (int idx = tid; idx < 2048; idx += 1024) {
        int row = idx >> 6, k = idx & 63;
        ti[row][k] = g_rn[((size_t)(b * SPIX + i0 + row)) * FEAT + k];
        tj[row][k] = g_rn[((size_t)(b * SPIX + j0 + row)) * FEAT + k];
    }
    __syncthreads();

    float acc = 0.0f;
#pragma unroll
    for (int k = 0; k < 64; k++) acc += ti[ty][k] * tj[tx][k];

    float istd = 1.0f / sqrtf(vr[0] + 1e-5f);
    float A = gma[0] * w_sim[0] * istd;
    float C = gma[0] * (b_sim[0] - mu[0]) * istd + bta[0];
    float y = fmaxf(A * acc + C, 0.0f);

    out[((size_t)(b * SPIX + i0 + ty)) * SPIX + j0 + tx] = y;
}

// ---------------------------------------------------------------------------
extern "C" void kernel_launch(void* const* d_in, const int* in_sizes, int n_in,
                              void* d_out, int out_size) {
    const float* x   = (const float*)d_in[0];
    const int*   lab = (const int*)d_in[1];
    // num_spixels may or may not appear as a size-1 input between labels and W_pix
    int o = (in_sizes[2] == 192) ? 2 : 3;
    const float* W_pix = (const float*)d_in[o];
    const float* b_pix = (const float*)d_in[o + 1];
    const float* W_red = (const float*)d_in[o + 2];
    const float* b_red = (const float*)d_in[o + 3];
    const float* w_sim = (const float*)d_in[o + 4];
    const float* b_sim = (const float*)d_in[o + 5];
    const float* gma   = (const float*)d_in[o + 6];
    const float* bta   = (const float*)d_in[o + 7];
    const float* mu    = (const float*)d_in[o + 8];
    const float* vr    = (const float*)d_in[o + 9];

    zero_kernel<<<96, 512>>>();
    moments_kernel<<<1024, 256>>>(x, lab);
    stats_kernel<<<256, 256>>>(W_pix, b_pix, W_red, b_red);
    dim3 g3(8, 8, 8), b3(32, 32);
    sim_kernel<<<g3, b3>>>(w_sim, b_sim, gma, bta, mu, vr, (float*)d_out);
}